// round 5
// baseline (speedup 1.0000x reference)
#include <cuda_runtime.h>
#include <math.h>
#include <stdint.h>

// Problem constants (fixed by the dataset)
#define BB 8
#define FF 16
#define NN 2048
#define JS 4
#define NCOLS 21          // 1 + 4 + 16
#define OUT_ELEMS (BB*FF*NCOLS)

// Scratch: S1[b][j][f][m] as 512 x 2048 row-major, row = (b*4+j)*16+f
__device__ float g_S1[BB * JS * FF * NN];

// ---------------------------------------------------------------------------
__global__ void zero_phi_kernel(float* __restrict__ out) {
    int i = blockIdx.x * blockDim.x + threadIdx.x;
    if (i < OUT_ELEMS) out[i] = 0.0f;
}

// phi0[b,f] = sum_n x[b,f,n]*lowpass[n]  — exact fp32 (signed sum, can be ~0)
__global__ void phi0_kernel(const float* __restrict__ x,
                            const float* __restrict__ lp,
                            float* __restrict__ out) {
    int r = blockIdx.x;
    const float* xr = x + (size_t)r * NN;
    float s = 0.0f;
    for (int n = threadIdx.x; n < NN; n += 256) s += xr[n] * lp[n];
    __shared__ float red[8];
    #pragma unroll
    for (int o = 16; o; o >>= 1) s += __shfl_xor_sync(0xffffffffu, s, o);
    if ((threadIdx.x & 31) == 0) red[threadIdx.x >> 5] = s;
    __syncthreads();
    if (threadIdx.x < 8) {
        s = red[threadIdx.x];
        #pragma unroll
        for (int o = 4; o; o >>= 1) s += __shfl_xor_sync(0xffu, s, o);
        if (threadIdx.x == 0) out[r * NCOLS + 0] = s;
    }
}

// ---------------------------------------------------------------------------
// Tensor-core fused GEMM (3xTF32 error-compensated) + |.| + lowpass epilogue.
//   Block tile 128x128, BK=16, 256 threads (8 warps = 4M x 2N, warp tile 32x64)
//   A smem [m][k] stride 20  -> frag-load bank (20g+t)%32 : conflict-free
//   B smem [k][n] stride 136 -> frag-load bank (8t+g)%32  : conflict-free
//   Each operand split hi/lo; 3 MMAs: lo_a*hi_b + hi_a*lo_b + hi_a*hi_b.
// ---------------------------------------------------------------------------
#define BM 128
#define BN 128
#define BKT 16
#define ASTR 20
#define BSTR 136

__device__ __forceinline__ void cp16(uint32_t s, const float* g) {
    asm volatile("cp.async.cg.shared.global [%0], [%1], 16;\n" :: "r"(s), "l"(g));
}

__device__ __forceinline__ uint32_t f2tf(float f) {
    uint32_t u;
    asm("cvt.rna.tf32.f32 %0, %1;\n" : "=r"(u) : "f"(f));
    return u;
}

#define MMA_TF32(C, A0, A1, A2, A3, B0, B1)                                  \
    asm volatile(                                                            \
        "mma.sync.aligned.m16n8k8.row.col.f32.tf32.tf32.f32 "                \
        "{%0,%1,%2,%3}, {%4,%5,%6,%7}, {%8,%9}, {%0,%1,%2,%3};\n"            \
        : "+f"((C)[0]), "+f"((C)[1]), "+f"((C)[2]), "+f"((C)[3])             \
        : "r"(A0), "r"(A1), "r"(A2), "r"(A3), "r"(B0), "r"(B1))

template <int LAYER>
__global__ __launch_bounds__(256, 1)
void gemm_mma_kernel(const float* __restrict__ Ain,
                     const float* __restrict__ psi,
                     const float* __restrict__ lp,
                     float* __restrict__ phi) {
    __shared__ __align__(16) float As[2][BM * ASTR];   // 20 KB
    __shared__ __align__(16) float Bs[2][BKT * BSTR];  // 17 KB

    const float* A = (LAYER == 1) ? Ain : g_S1;
    const int j   = blockIdx.z;
    const int m0  = blockIdx.y * BM;
    const int n0  = blockIdx.x * BN;
    const int tid = threadIdx.x;
    const int lane = tid & 31, w = tid >> 5;
    const int wm = w & 3;           // 4 warps in M (32 rows each)
    const int wn = w >> 2;          // 2 warps in N (64 cols each)
    const int g = lane >> 2, t = lane & 3;

    const float* B = psi + (size_t)j * NN * NN;

    // cp.async assignments
    const int arow = tid >> 2, akc = (tid & 3) * 4;     // rows arow, arow+64
    const int brow = tid >> 5, bnc = (tid & 31) * 4;    // rows brow, brow+8

    uint32_t sA0 = (uint32_t)__cvta_generic_to_shared(&As[0][0]);
    uint32_t sB0 = (uint32_t)__cvta_generic_to_shared(&Bs[0][0]);

    float c[2][8][4] = {};

    #define COPY_TILE(buf, k0)                                                         \
    do {                                                                               \
        uint32_t sA = sA0 + (buf) * (BM * ASTR * 4);                                   \
        uint32_t sB = sB0 + (buf) * (BKT * BSTR * 4);                                  \
        cp16(sA + (arow * ASTR + akc) * 4,        A + (size_t)(m0 + arow) * NN + (k0) + akc);      \
        cp16(sA + ((arow + 64) * ASTR + akc) * 4, A + (size_t)(m0 + arow + 64) * NN + (k0) + akc); \
        cp16(sB + (brow * BSTR + bnc) * 4,        B + (size_t)((k0) + brow) * NN + n0 + bnc);      \
        cp16(sB + ((brow + 8) * BSTR + bnc) * 4,  B + (size_t)((k0) + brow + 8) * NN + n0 + bnc);  \
        asm volatile("cp.async.commit_group;\n");                                      \
    } while (0)

    COPY_TILE(0, 0);

    const int nk = NN / BKT;   // 128
    for (int kt = 0; kt < nk; kt++) {
        const int buf = kt & 1;
        if (kt + 1 < nk) {
            COPY_TILE(buf ^ 1, (kt + 1) * BKT);
            asm volatile("cp.async.wait_group 1;\n");
        } else {
            asm volatile("cp.async.wait_group 0;\n");
        }
        __syncthreads();

        const float* as = &As[buf][0];
        const float* bs = &Bs[buf][0];
        #pragma unroll
        for (int kk = 0; kk < 2; kk++) {
            const int kb = kk * 8;
            uint32_t ah[2][4], al[2][4];
            #pragma unroll
            for (int mi = 0; mi < 2; mi++) {
                const int r = wm * 32 + mi * 16 + g;
                float f0 = as[(r)     * ASTR + kb + t];
                float f1 = as[(r + 8) * ASTR + kb + t];
                float f2 = as[(r)     * ASTR + kb + t + 4];
                float f3 = as[(r + 8) * ASTR + kb + t + 4];
                ah[mi][0] = f2tf(f0); al[mi][0] = f2tf(f0 - __uint_as_float(ah[mi][0]));
                ah[mi][1] = f2tf(f1); al[mi][1] = f2tf(f1 - __uint_as_float(ah[mi][1]));
                ah[mi][2] = f2tf(f2); al[mi][2] = f2tf(f2 - __uint_as_float(ah[mi][2]));
                ah[mi][3] = f2tf(f3); al[mi][3] = f2tf(f3 - __uint_as_float(ah[mi][3]));
            }
            // Capped unroll: hedge against ptxas blowup (96-MMA full unroll
            // suspected in the 2x container timeout). 4 iterations x 12 MMAs.
            #pragma unroll 4
            for (int ni = 0; ni < 8; ni++) {
                const int cn = wn * 64 + ni * 8 + g;
                float fb0 = bs[(kb + t)     * BSTR + cn];
                float fb1 = bs[(kb + t + 4) * BSTR + cn];
                uint32_t bh0 = f2tf(fb0), bh1 = f2tf(fb1);
                uint32_t bl0 = f2tf(fb0 - __uint_as_float(bh0));
                uint32_t bl1 = f2tf(fb1 - __uint_as_float(bh1));
                #pragma unroll
                for (int mi = 0; mi < 2; mi++) {
                    // small terms first, then dominant hi*hi
                    MMA_TF32(c[mi][ni], al[mi][0], al[mi][1], al[mi][2], al[mi][3], bh0, bh1);
                    MMA_TF32(c[mi][ni], ah[mi][0], ah[mi][1], ah[mi][2], ah[mi][3], bl0, bl1);
                    MMA_TF32(c[mi][ni], ah[mi][0], ah[mi][1], ah[mi][2], ah[mi][3], bh0, bh1);
                }
            }
        }
        __syncthreads();
    }

    // Epilogue: abs, optional S1 store, lowpass reduction, atomic phi update.
    // C frag mapping: c0=(row g, col 2t), c1=(g,2t+1), c2=(g+8,2t), c3=(g+8,2t+1)
    float p[2][2] = {};
    #pragma unroll
    for (int mi = 0; mi < 2; mi++) {
        #pragma unroll 4
        for (int ni = 0; ni < 8; ni++) {
            const int m = n0 + wn * 64 + ni * 8 + 2 * t;
            float v0 = fabsf(c[mi][ni][0]), v1 = fabsf(c[mi][ni][1]);
            float v2 = fabsf(c[mi][ni][2]), v3 = fabsf(c[mi][ni][3]);
            float l0 = __ldg(&lp[m]), l1 = __ldg(&lp[m + 1]);
            p[mi][0] += v0 * l0 + v1 * l1;
            p[mi][1] += v2 * l0 + v3 * l1;
            if (LAYER == 1) {
                const int r0 = m0 + wm * 32 + mi * 16 + g;
                int b0i = r0 >> 4, f0 = r0 & 15;
                int s1r0 = ((b0i * JS + j) << 4) + f0;
                *(float2*)&g_S1[(size_t)s1r0 * NN + m] = make_float2(v0, v1);
                const int r1 = r0 + 8;
                int b1i = r1 >> 4, f1 = r1 & 15;
                int s1r1 = ((b1i * JS + j) << 4) + f1;
                *(float2*)&g_S1[(size_t)s1r1 * NN + m] = make_float2(v2, v3);
            }
        }
    }
    #pragma unroll
    for (int mi = 0; mi < 2; mi++) {
        #pragma unroll
        for (int s = 0; s < 2; s++) {
            float v = p[mi][s];
            v += __shfl_xor_sync(0xffffffffu, v, 1);
            v += __shfl_xor_sync(0xffffffffu, v, 2);
            if (t == 0) {
                const int r = m0 + wm * 32 + mi * 16 + g + s * 8;
                int b, f, col;
                if (LAYER == 1) { b = r >> 4; f = r & 15; col = 1 + j; }
                else { b = r >> 6; int j1 = (r >> 4) & 3; f = r & 15; col = 5 + j1 * 4 + j; }
                atomicAdd(&phi[(b * FF + f) * NCOLS + col], v);
            }
        }
    }
    #undef COPY_TILE
}

// ---------------------------------------------------------------------------
extern "C" void kernel_launch(void* const* d_in, const int* in_sizes, int n_in,
                              void* d_out, int out_size) {
    const float* x   = (const float*)d_in[0];   // (8,16,2048)
    const float* psi = (const float*)d_in[1];   // (4,2048,2048)
    const float* lp  = (const float*)d_in[2];   // (2048,)
    float* out = (float*)d_out;                 // (8,16,21)
    (void)in_sizes; (void)n_in; (void)out_size;

    zero_phi_kernel<<<(OUT_ELEMS + 255) / 256, 256>>>(out);
    phi0_kernel<<<BB * FF, 256>>>(x, lp, out);
    // layer 1: M=128 -> 1 M-tile, 16 N-tiles, 4 j
    gemm_mma_kernel<1><<<dim3(16, 1, 4), 256>>>(x, psi, lp, out);
    // layer 2: M=512 -> 4 M-tiles, 16 N-tiles, 4 j
    gemm_mma_kernel<2><<<dim3(16, 4, 4), 256>>>(nullptr, psi, lp, out);
}

// round 7
// speedup vs baseline: 3.9161x; 3.9161x over previous
#include <cuda_runtime.h>
#include <cuda_fp16.h>
#include <math.h>
#include <stdint.h>

// Problem constants
#define BB 8
#define FF 16
#define NN 2048
#define JS 4
#define NCOLS 21
#define OUT_ELEMS (BB*FF*NCOLS)
#define NW2 (NN/2)               // 1024 packed words per row

// ---------------- packed hi/lo scratch (uint32 = 2 x fp16) ----------------
__device__ __align__(256) uint32_t g_X2h[BB*FF*NW2], g_X2l[BB*FF*NW2];        // x rows
__device__ __align__(256) uint32_t g_P2h[(size_t)JS*NN*NW2];                  // psi^T packed
__device__ __align__(256) uint32_t g_P2l[(size_t)JS*NN*NW2];
__device__ __align__(256) uint32_t g_S2h[(size_t)BB*JS*FF*NW2];               // S1 rows
__device__ __align__(256) uint32_t g_S2l[(size_t)BB*JS*FF*NW2];

// ---------------- helpers ----------------
__device__ __forceinline__ uint32_t smem_u32(const void* p) {
    uint32_t a;
    asm("{ .reg .u64 t; cvta.to.shared.u64 t, %1; cvt.u32.u64 %0, t; }" : "=r"(a) : "l"(p));
    return a;
}
__device__ __forceinline__ void cp16(uint32_t s, const void* g) {
    asm volatile("cp.async.cg.shared.global [%0], [%1], 16;\n" :: "r"(s), "l"(g));
}
__device__ __forceinline__ uint32_t pack2(float a, float b) {
    __half2 h = __floats2half2_rn(a, b);
    return *reinterpret_cast<uint32_t*>(&h);
}
#define MMA_F16(C, A, B0, B1)                                                 \
    asm volatile(                                                             \
        "mma.sync.aligned.m16n8k16.row.col.f32.f16.f16.f32 "                  \
        "{%0,%1,%2,%3}, {%4,%5,%6,%7}, {%8,%9}, {%0,%1,%2,%3};\n"             \
        : "+f"((C)[0]), "+f"((C)[1]), "+f"((C)[2]), "+f"((C)[3])              \
        : "r"((A)[0]), "r"((A)[1]), "r"((A)[2]), "r"((A)[3]), "r"(B0), "r"(B1))

// ---------------- small kernels ----------------
__global__ void zero_phi_kernel(float* __restrict__ out) {
    int i = blockIdx.x * blockDim.x + threadIdx.x;
    if (i < OUT_ELEMS) out[i] = 0.0f;
}

__global__ void phi0_kernel(const float* __restrict__ x, const float* __restrict__ lp,
                            float* __restrict__ out) {
    int r = blockIdx.x;
    const float* xr = x + (size_t)r * NN;
    float s = 0.0f;
    for (int n = threadIdx.x; n < NN; n += 256) s += xr[n] * lp[n];
    __shared__ float red[8];
    #pragma unroll
    for (int o = 16; o; o >>= 1) s += __shfl_xor_sync(0xffffffffu, s, o);
    if ((threadIdx.x & 31) == 0) red[threadIdx.x >> 5] = s;
    __syncthreads();
    if (threadIdx.x < 8) {
        s = red[threadIdx.x];
        #pragma unroll
        for (int o = 4; o; o >>= 1) s += __shfl_xor_sync(0xffu, s, o);
        if (threadIdx.x == 0) out[r * NCOLS + 0] = s;
    }
}

// x -> packed fp16 hi/lo pairs (k-contiguous, natural layout)
__global__ void split_pack_x(const float* __restrict__ x) {
    int i = blockIdx.x * blockDim.x + threadIdx.x;
    if (i < BB * FF * NW2) {
        float a = x[2 * i], b = x[2 * i + 1];
        float ah = __half2float(__float2half_rn(a));
        float bh = __half2float(__float2half_rn(b));
        g_X2h[i] = pack2(a, b);
        g_X2l[i] = pack2(a - ah, b - bh);
    }
}

// psi[j][n][m] -> P2[j][m][n2] packed pairs along n (transpose + split)
__global__ void transpose_pack_psi(const float* __restrict__ psi) {
    __shared__ float sm[32][33];
    const int j = blockIdx.z;
    const int m0 = blockIdx.x * 32, n0 = blockIdx.y * 32;
    const int tid = threadIdx.x;
    const float* P = psi + (size_t)j * NN * NN;
    #pragma unroll
    for (int it = 0; it < 4; it++) {
        int idx = it * 256 + tid;
        int nl = idx >> 5, ml = idx & 31;
        sm[nl][ml] = P[(size_t)(n0 + nl) * NN + m0 + ml];
    }
    __syncthreads();
    const size_t obase = (size_t)j * NN * NW2 + (size_t)(n0 >> 1);
    #pragma unroll
    for (int it = 0; it < 2; it++) {
        int flat = it * 256 + tid;            // 512 words: 32 m x 16 n2
        int ml = flat >> 4, n2l = flat & 15;
        float a = sm[2 * n2l][ml], b = sm[2 * n2l + 1][ml];
        float ah = __half2float(__float2half_rn(a));
        float bh = __half2float(__float2half_rn(b));
        size_t o = obase + (size_t)(m0 + ml) * NW2 + n2l;
        g_P2h[o] = pack2(a, b);
        g_P2l[o] = pack2(a - ah, b - bh);
    }
}

// ---------------- fused fp16 3-term tensor GEMM ----------------
// C[r,m] = sum_n A[r,n]*psi[n,m]; 128x128 tile, BK=32, 256 thr, 8 warps (4M x 2N).
// smem planes (Ah,Al,Bh,Bl): 128 rows x 16 words, stride 20 words (80B) ->
// frag-load bank = (20*row + t) % 32, conflict-free. Double buffered: 80 KB.
#define PLW 2560                 // words per plane (128*20)
#define NKC 64                   // 2048/32 chunks
#define SMEM_BYTES (2*4*PLW*4)   // 81920

template <int LAYER>
__global__ __launch_bounds__(256, 2)
void gemm_f16(const float* __restrict__ lp, float* __restrict__ phi) {
    extern __shared__ __align__(1024) uint32_t smw[];
    const int tid = threadIdx.x;
    const int lane = tid & 31, w = tid >> 5;
    const int wm = w & 3, wn = w >> 2;
    const int g = lane >> 2, t = lane & 3;
    const int j  = blockIdx.z;
    const int n0 = blockIdx.x * 128, m0 = blockIdx.y * 128;

    const uint32_t* Agh = ((LAYER == 1) ? g_X2h : g_S2h) + (size_t)m0 * NW2;
    const uint32_t* Agl = ((LAYER == 1) ? g_X2l : g_S2l) + (size_t)m0 * NW2;
    const uint32_t* Bgh = g_P2h + (size_t)j * NN * NW2 + (size_t)n0 * NW2;
    const uint32_t* Bgl = g_P2l + (size_t)j * NN * NW2 + (size_t)n0 * NW2;
    const uint32_t* srcs[4] = { Agh, Agl, Bgh, Bgl };

    const uint32_t sb = smem_u32(smw);
    const int row = tid >> 2, cc = tid & 3;    // 16B chunk assignment

    auto copy_stage = [&](int buf, int kc) {
        #pragma unroll
        for (int pl = 0; pl < 4; pl++) {
            uint32_t pb = sb + (uint32_t)(buf * 4 + pl) * (PLW * 4);
            const uint32_t* s = srcs[pl] + kc * 16;
            #pragma unroll
            for (int i = 0; i < 2; i++) {
                int r2 = row + i * 64;
                cp16(pb + r2 * 80 + cc * 16, s + (size_t)r2 * NW2 + cc * 4);
            }
        }
        asm volatile("cp.async.commit_group;\n");
    };

    float c[2][8][4] = {};

    copy_stage(0, 0);
    for (int kt = 0; kt < NKC; kt++) {
        const int buf = kt & 1;
        if (kt + 1 < NKC) {
            copy_stage(buf ^ 1, kt + 1);
            asm volatile("cp.async.wait_group 1;\n");
        } else {
            asm volatile("cp.async.wait_group 0;\n");
        }
        __syncthreads();

        const uint32_t* Ahs = smw + (buf * 4 + 0) * PLW;
        const uint32_t* Als = smw + (buf * 4 + 1) * PLW;
        const uint32_t* Bhs = smw + (buf * 4 + 2) * PLW;
        const uint32_t* Bls = smw + (buf * 4 + 3) * PLW;

        #pragma unroll
        for (int kk = 0; kk < 2; kk++) {
            const int kq = kk * 8;
            uint32_t ah[2][4], al[2][4];
            #pragma unroll
            for (int mi = 0; mi < 2; mi++) {
                const int r = wm * 32 + mi * 16 + g;
                ah[mi][0] = Ahs[(r)     * 20 + kq + t];
                ah[mi][1] = Ahs[(r + 8) * 20 + kq + t];
                ah[mi][2] = Ahs[(r)     * 20 + kq + t + 4];
                ah[mi][3] = Ahs[(r + 8) * 20 + kq + t + 4];
                al[mi][0] = Als[(r)     * 20 + kq + t];
                al[mi][1] = Als[(r + 8) * 20 + kq + t];
                al[mi][2] = Als[(r)     * 20 + kq + t + 4];
                al[mi][3] = Als[(r + 8) * 20 + kq + t + 4];
            }
            // term-outer / ni-inner: dependency distance 16 to same accumulator
            #pragma unroll
            for (int term = 0; term < 3; term++) {
                const uint32_t (*af)[4] = (term == 0) ? al : ah;
                const uint32_t* Bp = (term == 1) ? Bls : Bhs;
                #pragma unroll
                for (int ni = 0; ni < 8; ni++) {
                    const int col = wn * 64 + ni * 8 + g;
                    uint32_t b0 = Bp[col * 20 + kq + t];
                    uint32_t b1 = Bp[col * 20 + kq + t + 4];
                    MMA_F16(c[0][ni], af[0], b0, b1);
                    MMA_F16(c[1][ni], af[1], b0, b1);
                }
            }
        }
        __syncthreads();
    }

    // Epilogue: abs + lowpass partials; layer-1 packs S1 hi/lo.
    // c0=(g,2t) c1=(g,2t+1) c2=(g+8,2t) c3=(g+8,2t+1)
    float p[2][2] = {};
    #pragma unroll
    for (int mi = 0; mi < 2; mi++) {
        #pragma unroll
        for (int ni = 0; ni < 8; ni++) {
            const int m = n0 + wn * 64 + ni * 8 + 2 * t;
            float v0 = fabsf(c[mi][ni][0]), v1 = fabsf(c[mi][ni][1]);
            float v2 = fabsf(c[mi][ni][2]), v3 = fabsf(c[mi][ni][3]);
            float l0 = __ldg(&lp[m]), l1 = __ldg(&lp[m + 1]);
            p[mi][0] += v0 * l0 + v1 * l1;
            p[mi][1] += v2 * l0 + v3 * l1;
            if (LAYER == 1) {
                const int r0 = m0 + wm * 32 + mi * 16 + g;
                const int r1 = r0 + 8;
                int s0 = (((r0 >> 4) * JS + j) << 4) + (r0 & 15);
                int s1 = (((r1 >> 4) * JS + j) << 4) + (r1 & 15);
                float h0 = __half2float(__float2half_rn(v0));
                float h1 = __half2float(__float2half_rn(v1));
                float h2 = __half2float(__float2half_rn(v2));
                float h3 = __half2float(__float2half_rn(v3));
                g_S2h[(size_t)s0 * NW2 + (m >> 1)] = pack2(v0, v1);
                g_S2l[(size_t)s0 * NW2 + (m >> 1)] = pack2(v0 - h0, v1 - h1);
                g_S2h[(size_t)s1 * NW2 + (m >> 1)] = pack2(v2, v3);
                g_S2l[(size_t)s1 * NW2 + (m >> 1)] = pack2(v2 - h2, v3 - h3);
            }
        }
    }
    #pragma unroll
    for (int mi = 0; mi < 2; mi++) {
        #pragma unroll
        for (int s = 0; s < 2; s++) {
            float v = p[mi][s];
            v += __shfl_xor_sync(0xffffffffu, v, 1);
            v += __shfl_xor_sync(0xffffffffu, v, 2);
            if (t == 0) {
                const int r = m0 + wm * 32 + mi * 16 + g + s * 8;
                int b, f, col;
                if (LAYER == 1) { b = r >> 4; f = r & 15; col = 1 + j; }
                else { b = r >> 6; int j1 = (r >> 4) & 3; f = r & 15; col = 5 + j1 * 4 + j; }
                atomicAdd(&phi[(b * FF + f) * NCOLS + col], v);
            }
        }
    }
}

// ---------------- launch ----------------
extern "C" void kernel_launch(void* const* d_in, const int* in_sizes, int n_in,
                              void* d_out, int out_size) {
    const float* x   = (const float*)d_in[0];   // (8,16,2048)
    const float* psi = (const float*)d_in[1];   // (4,2048,2048)
    const float* lp  = (const float*)d_in[2];   // (2048,)
    float* out = (float*)d_out;                 // (8,16,21)
    (void)in_sizes; (void)n_in; (void)out_size;

    cudaFuncSetAttribute(gemm_f16<1>, cudaFuncAttributeMaxDynamicSharedMemorySize, SMEM_BYTES);
    cudaFuncSetAttribute(gemm_f16<2>, cudaFuncAttributeMaxDynamicSharedMemorySize, SMEM_BYTES);

    zero_phi_kernel<<<(OUT_ELEMS + 255) / 256, 256>>>(out);
    phi0_kernel<<<BB * FF, 256>>>(x, lp, out);
    split_pack_x<<<(BB * FF * NW2 + 255) / 256, 256>>>(x);
    transpose_pack_psi<<<dim3(NN / 32, NN / 32, JS), 256>>>(psi);
    // layer 1: M=128 (1 tile) x 16 N-tiles x 4 j
    gemm_f16<1><<<dim3(16, 1, 4), 256, SMEM_BYTES>>>(lp, out);
    // layer 2: M=512 (4 tiles) x 16 N-tiles x 4 j
    gemm_f16<2><<<dim3(16, 4, 4), 256, SMEM_BYTES>>>(lp, out);
}

// round 8
// speedup vs baseline: 4.5694x; 1.1668x over previous
#include <cuda_runtime.h>
#include <cuda_fp16.h>
#include <math.h>
#include <stdint.h>

// Problem constants
#define BB 8
#define FF 16
#define NN 2048
#define JS 4
#define NCOLS 21
#define OUT_ELEMS (BB*FF*NCOLS)
#define NW2 (NN/2)               // 1024 packed fp16-pair words per row

// ---------------- packed hi/lo scratch (uint32 = 2 x fp16) ----------------
__device__ __align__(256) uint32_t g_X2h[BB*FF*NW2], g_X2l[BB*FF*NW2];
__device__ __align__(256) uint32_t g_P2h[(size_t)JS*NN*NW2];
__device__ __align__(256) uint32_t g_P2l[(size_t)JS*NN*NW2];
__device__ __align__(256) uint32_t g_S2h[(size_t)BB*JS*FF*NW2];
__device__ __align__(256) uint32_t g_S2l[(size_t)BB*JS*FF*NW2];

// ---------------- helpers ----------------
__device__ __forceinline__ uint32_t smem_u32(const void* p) {
    uint32_t a;
    asm("{ .reg .u64 t; cvta.to.shared.u64 t, %1; cvt.u32.u64 %0, t; }" : "=r"(a) : "l"(p));
    return a;
}
__device__ __forceinline__ void cp16(uint32_t s, const void* g) {
    asm volatile("cp.async.cg.shared.global [%0], [%1], 16;\n" :: "r"(s), "l"(g));
}
__device__ __forceinline__ uint32_t pack2(float a, float b) {
    __half2 h = __floats2half2_rn(a, b);
    return *reinterpret_cast<uint32_t*>(&h);
}
#define MMA_F16(C, A, B0, B1)                                                 \
    asm volatile(                                                             \
        "mma.sync.aligned.m16n8k16.row.col.f32.f16.f16.f32 "                  \
        "{%0,%1,%2,%3}, {%4,%5,%6,%7}, {%8,%9}, {%0,%1,%2,%3};\n"             \
        : "+f"((C)[0]), "+f"((C)[1]), "+f"((C)[2]), "+f"((C)[3])              \
        : "r"((A)[0]), "r"((A)[1]), "r"((A)[2]), "r"((A)[3]), "r"(B0), "r"(B1))
#define LDSM4(R, addr)                                                        \
    asm volatile("ldmatrix.sync.aligned.m8n8.x4.shared.b16 {%0,%1,%2,%3}, [%4];" \
        : "=r"((R)[0]), "=r"((R)[1]), "=r"((R)[2]), "=r"((R)[3]) : "r"(addr))

// ---------------- small kernels ----------------
__global__ void zero_phi_kernel(float* __restrict__ out) {
    int i = blockIdx.x * blockDim.x + threadIdx.x;
    if (i < OUT_ELEMS) out[i] = 0.0f;
}

__global__ void phi0_kernel(const float* __restrict__ x, const float* __restrict__ lp,
                            float* __restrict__ out) {
    int r = blockIdx.x;
    const float* xr = x + (size_t)r * NN;
    float s = 0.0f;
    for (int n = threadIdx.x; n < NN; n += 256) s += xr[n] * lp[n];
    __shared__ float red[8];
    #pragma unroll
    for (int o = 16; o; o >>= 1) s += __shfl_xor_sync(0xffffffffu, s, o);
    if ((threadIdx.x & 31) == 0) red[threadIdx.x >> 5] = s;
    __syncthreads();
    if (threadIdx.x < 8) {
        s = red[threadIdx.x];
        #pragma unroll
        for (int o = 4; o; o >>= 1) s += __shfl_xor_sync(0xffu, s, o);
        if (threadIdx.x == 0) out[r * NCOLS + 0] = s;
    }
}

__global__ void split_pack_x(const float* __restrict__ x) {
    int i = blockIdx.x * blockDim.x + threadIdx.x;
    if (i < BB * FF * NW2) {
        float a = x[2 * i], b = x[2 * i + 1];
        float ah = __half2float(__float2half_rn(a));
        float bh = __half2float(__float2half_rn(b));
        g_X2h[i] = pack2(a, b);
        g_X2l[i] = pack2(a - ah, b - bh);
    }
}

// psi[j][n][m] -> P2[j][m][n2] packed pairs along n (transpose + split)
__global__ void transpose_pack_psi(const float* __restrict__ psi) {
    __shared__ float sm[32][33];
    const int j = blockIdx.z;
    const int m0 = blockIdx.x * 32, n0 = blockIdx.y * 32;
    const int tid = threadIdx.x;
    const float* P = psi + (size_t)j * NN * NN;
    #pragma unroll
    for (int it = 0; it < 4; it++) {
        int idx = it * 256 + tid;
        int nl = idx >> 5, ml = idx & 31;
        sm[nl][ml] = P[(size_t)(n0 + nl) * NN + m0 + ml];
    }
    __syncthreads();
    const size_t obase = (size_t)j * NN * NW2 + (size_t)(n0 >> 1);
    #pragma unroll
    for (int it = 0; it < 2; it++) {
        int flat = it * 256 + tid;
        int ml = flat >> 4, n2l = flat & 15;
        float a = sm[2 * n2l][ml], b = sm[2 * n2l + 1][ml];
        float ah = __half2float(__float2half_rn(a));
        float bh = __half2float(__float2half_rn(b));
        size_t o = obase + (size_t)(m0 + ml) * NW2 + n2l;
        g_P2h[o] = pack2(a, b);
        g_P2l[o] = pack2(a - ah, b - bh);
    }
}

// ---------------- fused fp16 3-term tensor GEMM (ldmatrix edition) ----------
// Tile 128 x TN (TN=16*NI), BK=32, 256 thr, 8 warps (4M x 2N).
// smem planes (Ah,Al,Bh,Bl), 80 B/row (stride-20 words): ldmatrix conflict-free.
template <int LAYER, int NI>
__global__ __launch_bounds__(256, 2)
void gemm_f16(const float* __restrict__ lp, float* __restrict__ phi) {
    constexpr int TN  = NI * 16;
    constexpr int APL = 128 * 80;            // A plane bytes (10240)
    constexpr int BPL = TN * 80;             // B plane bytes
    constexpr int STB = 2 * APL + 2 * BPL;   // stage bytes
    constexpr int NKC = 64;                  // 2048/32 k-chunks

    extern __shared__ __align__(1024) char smc[];
    const uint32_t sb = smem_u32(smc);
    const int tid = threadIdx.x;
    const int lane = tid & 31, w = tid >> 5;
    const int wm = w & 3, wn = w >> 2;
    const int g = lane >> 2, t = lane & 3;
    const int j  = blockIdx.z;
    const int n0 = blockIdx.x * TN, m0 = blockIdx.y * 128;

    const uint32_t* srcs[4] = {
        ((LAYER == 1) ? g_X2h : g_S2h) + (size_t)m0 * NW2,
        ((LAYER == 1) ? g_X2l : g_S2l) + (size_t)m0 * NW2,
        g_P2h + (size_t)j * NN * NW2 + (size_t)n0 * NW2,
        g_P2l + (size_t)j * NN * NW2 + (size_t)n0 * NW2 };

    // per-lane ldmatrix base offsets (bytes within plane)
    const int lrow = lane & 7, lm = lane >> 3;
    uint32_t aoff[2];
    #pragma unroll
    for (int mi = 0; mi < 2; mi++)
        aoff[mi] = (uint32_t)((wm * 32 + mi * 16 + (lm & 1) * 8 + lrow) * 80
                              + (lm >> 1) * 16);
    const uint32_t boff = (uint32_t)((wn * NI * 8 + (lm >> 1) * 8 + lrow) * 80
                                     + (lm & 1) * 16);

    auto copy_stage = [&](int buf, int kc) {
        uint32_t st = sb + buf * STB;
        #pragma unroll
        for (int pl = 0; pl < 2; pl++) {                 // A planes: 128 rows
            uint32_t pb = st + pl * APL;
            const uint32_t* s = srcs[pl] + kc * 16;
            #pragma unroll
            for (int i = 0; i < 2; i++) {
                int cid = i * 256 + tid, row = cid >> 2, cc = cid & 3;
                cp16(pb + row * 80 + cc * 16, s + (size_t)row * NW2 + cc * 4);
            }
        }
        constexpr int BPC = (TN * 4) / 256;              // chunks/thread per B plane
        #pragma unroll
        for (int pl = 0; pl < 2; pl++) {                 // B planes: TN rows
            uint32_t pb = st + 2 * APL + pl * BPL;
            const uint32_t* s = srcs[2 + pl] + kc * 16;
            #pragma unroll
            for (int i = 0; i < BPC; i++) {
                int cid = i * 256 + tid, row = cid >> 2, cc = cid & 3;
                cp16(pb + row * 80 + cc * 16, s + (size_t)row * NW2 + cc * 4);
            }
        }
        asm volatile("cp.async.commit_group;\n");
    };

    float c[2][NI][4] = {};

    copy_stage(0, 0);
    for (int kt = 0; kt < NKC; kt++) {
        const int buf = kt & 1;
        if (kt + 1 < NKC) {
            copy_stage(buf ^ 1, kt + 1);
            asm volatile("cp.async.wait_group 1;\n");
        } else {
            asm volatile("cp.async.wait_group 0;\n");
        }
        __syncthreads();

        const uint32_t st = sb + buf * STB;
        #pragma unroll
        for (int kk = 0; kk < 2; kk++) {
            const uint32_t kb = kk * 32;
            uint32_t ah[2][4], al[2][4], bh[NI / 2][4];
            LDSM4(ah[0], st + aoff[0] + kb);
            LDSM4(ah[1], st + aoff[1] + kb);
            LDSM4(al[0], st + APL + aoff[0] + kb);
            LDSM4(al[1], st + APL + aoff[1] + kb);
            #pragma unroll
            for (int q = 0; q < NI / 2; q++)
                LDSM4(bh[q], st + 2 * APL + boff + q * 1280 + kb);

            // term 0: Al x Bh  (cached Bh)
            #pragma unroll
            for (int ni = 0; ni < NI; ni++) {
                uint32_t b0 = bh[ni >> 1][(ni & 1) * 2], b1 = bh[ni >> 1][(ni & 1) * 2 + 1];
                MMA_F16(c[0][ni], al[0], b0, b1);
                MMA_F16(c[1][ni], al[1], b0, b1);
            }
            // term 1: Ah x Bl  (streamed Bl)
            #pragma unroll
            for (int q = 0; q < NI / 2; q++) {
                uint32_t bl[4];
                LDSM4(bl, st + 2 * APL + BPL + boff + q * 1280 + kb);
                #pragma unroll
                for (int s = 0; s < 2; s++) {
                    MMA_F16(c[0][q * 2 + s], ah[0], bl[s * 2], bl[s * 2 + 1]);
                    MMA_F16(c[1][q * 2 + s], ah[1], bl[s * 2], bl[s * 2 + 1]);
                }
            }
            // term 2: Ah x Bh  (cached Bh)
            #pragma unroll
            for (int ni = 0; ni < NI; ni++) {
                uint32_t b0 = bh[ni >> 1][(ni & 1) * 2], b1 = bh[ni >> 1][(ni & 1) * 2 + 1];
                MMA_F16(c[0][ni], ah[0], b0, b1);
                MMA_F16(c[1][ni], ah[1], b0, b1);
            }
        }
        __syncthreads();
    }

    // Epilogue: abs + lowpass partials; layer-1 packs S1 hi/lo.
    float p[2][2] = {};
    #pragma unroll
    for (int mi = 0; mi < 2; mi++) {
        #pragma unroll
        for (int ni = 0; ni < NI; ni++) {
            const int m = n0 + wn * NI * 8 + ni * 8 + 2 * t;
            float v0 = fabsf(c[mi][ni][0]), v1 = fabsf(c[mi][ni][1]);
            float v2 = fabsf(c[mi][ni][2]), v3 = fabsf(c[mi][ni][3]);
            float l0 = __ldg(&lp[m]), l1 = __ldg(&lp[m + 1]);
            p[mi][0] += v0 * l0 + v1 * l1;
            p[mi][1] += v2 * l0 + v3 * l1;
            if (LAYER == 1) {
                const int r0 = m0 + wm * 32 + mi * 16 + g;
                const int r1 = r0 + 8;
                int s0 = (((r0 >> 4) * JS + j) << 4) + (r0 & 15);
                int s1 = (((r1 >> 4) * JS + j) << 4) + (r1 & 15);
                float h0 = __half2float(__float2half_rn(v0));
                float h1 = __half2float(__float2half_rn(v1));
                float h2 = __half2float(__float2half_rn(v2));
                float h3 = __half2float(__float2half_rn(v3));
                g_S2h[(size_t)s0 * NW2 + (m >> 1)] = pack2(v0, v1);
                g_S2l[(size_t)s0 * NW2 + (m >> 1)] = pack2(v0 - h0, v1 - h1);
                g_S2h[(size_t)s1 * NW2 + (m >> 1)] = pack2(v2, v3);
                g_S2l[(size_t)s1 * NW2 + (m >> 1)] = pack2(v2 - h2, v3 - h3);
            }
        }
    }
    #pragma unroll
    for (int mi = 0; mi < 2; mi++) {
        #pragma unroll
        for (int s = 0; s < 2; s++) {
            float v = p[mi][s];
            v += __shfl_xor_sync(0xffffffffu, v, 1);
            v += __shfl_xor_sync(0xffffffffu, v, 2);
            if (t == 0) {
                const int r = m0 + wm * 32 + mi * 16 + g + s * 8;
                int b, f, col;
                if (LAYER == 1) { b = r >> 4; f = r & 15; col = 1 + j; }
                else { b = r >> 6; int j1 = (r >> 4) & 3; f = r & 15; col = 5 + j1 * 4 + j; }
                atomicAdd(&phi[(b * FF + f) * NCOLS + col], v);
            }
        }
    }
}

// ---------------- launch ----------------
extern "C" void kernel_launch(void* const* d_in, const int* in_sizes, int n_in,
                              void* d_out, int out_size) {
    const float* x   = (const float*)d_in[0];   // (8,16,2048)
    const float* psi = (const float*)d_in[1];   // (4,2048,2048)
    const float* lp  = (const float*)d_in[2];   // (2048,)
    float* out = (float*)d_out;                 // (8,16,21)
    (void)in_sizes; (void)n_in; (void)out_size;

    constexpr int SM1 = 2 * (2 * 128 * 80 + 2 * 64 * 80);    // 61440 (NI=4)
    constexpr int SM2 = 2 * (2 * 128 * 80 + 2 * 128 * 80);   // 81920 (NI=8)
    cudaFuncSetAttribute(gemm_f16<1, 4>, cudaFuncAttributeMaxDynamicSharedMemorySize, SM1);
    cudaFuncSetAttribute(gemm_f16<2, 8>, cudaFuncAttributeMaxDynamicSharedMemorySize, SM2);

    zero_phi_kernel<<<(OUT_ELEMS + 255) / 256, 256>>>(out);
    phi0_kernel<<<BB * FF, 256>>>(x, lp, out);
    split_pack_x<<<(BB * FF * NW2 + 255) / 256, 256>>>(x);
    transpose_pack_psi<<<dim3(NN / 32, NN / 32, JS), 256>>>(psi);
    // layer 1: TN=64 -> 32 N-tiles x 1 M-tile x 4 j = 128 CTAs
    gemm_f16<1, 4><<<dim3(32, 1, 4), 256, SM1>>>(lp, out);
    // layer 2: TN=128 -> 16 N-tiles x 4 M-tiles x 4 j = 256 CTAs
    gemm_f16<2, 8><<<dim3(16, 4, 4), 256, SM2>>>(lp, out);
}